// round 1
// baseline (speedup 1.0000x reference)
#include <cuda_runtime.h>
#include <math.h>

#define NN 100000
#define NF 16
#define C1 128
#define C2 256
#define MAXE 800000
#define EPSV 1e-5f

// ---------------- scratch (static device arrays; no allocation) ----------------
__device__ float g_aggx[NN * NF];
__device__ float g_deg[NN];
__device__ float g_rdeg[NN];
__device__ float g_h1[NN * C1];
__device__ float g_agg1[NN * C1];
__device__ float g_h2pre[NN * C2];
__device__ float g_u[NN * C1];
__device__ float g_v[NN * C1];
__device__ float g_stats1[2 * C1];
__device__ float g_stats2[2 * C2];

// ---------------- helpers ----------------
__device__ __forceinline__ unsigned long long pk2(float lo, float hi) {
    unsigned long long r;
    asm("mov.b64 %0, {%1, %2};" : "=l"(r) : "r"(__float_as_uint(lo)), "r"(__float_as_uint(hi)));
    return r;
}
__device__ __forceinline__ void fma2(unsigned long long& d, unsigned long long a, unsigned long long b) {
    asm("fma.rn.f32x2 %0, %1, %2, %0;" : "+l"(d) : "l"(a), "l"(b));
}
__device__ __forceinline__ float2 upk2(unsigned long long v) {
    unsigned int a, b;
    asm("mov.b64 {%0, %1}, %2;" : "=r"(a), "=r"(b) : "l"(v));
    float2 r; r.x = __uint_as_float(a); r.y = __uint_as_float(b);
    return r;
}
__device__ __forceinline__ void red_add_v4(float* p, float4 v) {
    asm volatile("red.global.add.v4.f32 [%0], {%1, %2, %3, %4};"
                 :: "l"(p), "f"(v.x), "f"(v.y), "f"(v.z), "f"(v.w) : "memory");
}
__device__ __forceinline__ float lrelu(float y) { return y > 0.f ? y : 0.01f * y; }

// ---------------- K0: init aggx = x (self loop), deg = 1, zero stats ----------------
__global__ void k_init(const float* __restrict__ x, int n) {
    int i = blockIdx.x * blockDim.x + threadIdx.x;
    int tot = n * NF / 4;
    if (i < tot) ((float4*)g_aggx)[i] = ((const float4*)x)[i];
    if (i < n) g_deg[i] = 1.f;
    if (i < 2 * C1) g_stats1[i] = 0.f;
    if (i < 2 * C2) g_stats2[i] = 0.f;
}

// ---------------- K1: scatter x into aggx, count deg ----------------
__global__ void k_scatter_x(const int* __restrict__ src, const int* __restrict__ dst,
                            const float* __restrict__ x, int E) {
    int e = blockIdx.x * blockDim.x + threadIdx.x;
    if (e >= E) return;
    int s = src[e], d = dst[e];
    const float4* xs = (const float4*)(x + (size_t)s * NF);
    float* ad = g_aggx + (size_t)d * NF;
    red_add_v4(ad + 0, xs[0]);
    red_add_v4(ad + 4, xs[1]);
    red_add_v4(ad + 8, xs[2]);
    red_add_v4(ad + 12, xs[3]);
    atomicAdd(&g_deg[d], 1.f);
}

__global__ void k_rdeg(int n) {
    int i = blockIdx.x * blockDim.x + threadIdx.x;
    if (i < n) g_rdeg[i] = 1.f / g_deg[i];
}

// ---------------- K2: h1pre = (aggx/deg) @ W1 + b1, accumulate BN stats ----------------
__global__ __launch_bounds__(128) void k_gcn1(const float* __restrict__ W1,
                                              const float* __restrict__ b1, int n) {
    __shared__ float W1s[NF * C1];
    __shared__ float xs[64 * NF];
    __shared__ float rds[64];
    int t = threadIdx.x;  // 128
    #pragma unroll
    for (int k = 0; k < NF; k++) W1s[k * C1 + t] = W1[k * C1 + t];
    int n0 = blockIdx.x * 64;
    for (int i = t; i < 64 * NF; i += 128) {
        int nn = n0 + (i >> 4);
        xs[i] = (nn < n) ? g_aggx[(size_t)nn * NF + (i & 15)] : 0.f;
    }
    if (t < 64) rds[t] = (n0 + t < n) ? g_rdeg[n0 + t] : 0.f;
    __syncthreads();
    int c = t;
    float bc = b1[c];
    float s = 0.f, q = 0.f;
    for (int j = 0; j < 64; j++) {
        int nn = n0 + j;
        if (nn >= n) break;
        float acc = 0.f;
        #pragma unroll
        for (int k = 0; k < NF; k++) acc = fmaf(xs[j * NF + k], W1s[k * C1 + c], acc);
        float h = fmaf(acc, rds[j], bc);
        g_h1[(size_t)nn * C1 + c] = h;
        s += h; q += h * h;
    }
    atomicAdd(&g_stats1[c], s);
    atomicAdd(&g_stats1[C1 + c], q);
}

// ---------------- K3: BN + leaky relu on h1; also init agg1 (self loop) ----------------
__global__ void k_bn1(const float* __restrict__ gamma, const float* __restrict__ beta,
                      float nf, int n) {
    int i = blockIdx.x * blockDim.x + threadIdx.x;
    int tot = n * (C1 / 4);
    if (i >= tot) return;
    int cb = (i & (C1 / 4 - 1)) * 4;
    float4 h = ((const float4*)g_h1)[i];
    float hv[4] = {h.x, h.y, h.z, h.w};
    float o[4];
    #pragma unroll
    for (int c = 0; c < 4; c++) {
        float mu = g_stats1[cb + c] / nf;
        float var = g_stats1[C1 + cb + c] / nf - mu * mu;
        float sc = gamma[cb + c] * rsqrtf(var + EPSV);
        o[c] = lrelu(fmaf(sc, hv[c] - mu, beta[cb + c]));
    }
    float4 r = make_float4(o[0], o[1], o[2], o[3]);
    ((float4*)g_h1)[i] = r;
    ((float4*)g_agg1)[i] = r;
}

// ---------------- K4: scatter h1 into agg1 ----------------
__global__ void k_scatter_h(const int* __restrict__ src, const int* __restrict__ dst, int E) {
    int t = blockIdx.x * blockDim.x + threadIdx.x;
    if (t >= E * 8) return;
    int e = t >> 3;
    int ch = (t & 7) * 16;
    int s = src[e], d = dst[e];
    const float4* hs = (const float4*)(g_h1 + (size_t)s * C1 + ch);
    float* ad = g_agg1 + (size_t)d * C1 + ch;
    red_add_v4(ad + 0, hs[0]);
    red_add_v4(ad + 4, hs[1]);
    red_add_v4(ad + 8, hs[2]);
    red_add_v4(ad + 12, hs[3]);
}

// ---------------- K5: h2pre = (agg1/deg) @ W2 + b2, BN stats ----------------
__global__ __launch_bounds__(256) void k_gcn2(const float* __restrict__ W2,
                                              const float* __restrict__ b2, int n) {
    __shared__ float As[64 * 32];
    __shared__ float Bs[32 * C2];
    __shared__ float rds[64];
    int t = threadIdx.x;
    int tx = t & 31, ty = t >> 5;
    int n0 = blockIdx.x * 64;
    if (t < 64) rds[t] = (n0 + t < n) ? g_rdeg[n0 + t] : 0.f;
    unsigned long long acc[8][4];
    #pragma unroll
    for (int i = 0; i < 8; i++)
        #pragma unroll
        for (int p = 0; p < 4; p++) acc[i][p] = 0ull;
    for (int kk = 0; kk < C1; kk += 32) {
        __syncthreads();
        for (int i = t; i < 64 * 32; i += 256) {
            int nn = n0 + (i >> 5);
            As[i] = (nn < n) ? g_agg1[(size_t)nn * C1 + kk + (i & 31)] * rds[i >> 5] : 0.f;
        }
        for (int i = t; i < 32 * C2 / 4; i += 256)
            ((float4*)Bs)[i] = ((const float4*)(W2 + (size_t)kk * C2))[i];
        __syncthreads();
        #pragma unroll 8
        for (int k = 0; k < 32; k++) {
            unsigned long long av[8], bp[4];
            float bs[8];
            #pragma unroll
            for (int i = 0; i < 8; i++) { float a = As[(ty * 8 + i) * 32 + k]; av[i] = pk2(a, a); }
            #pragma unroll
            for (int j = 0; j < 8; j++) bs[j] = Bs[k * C2 + tx + 32 * j];
            #pragma unroll
            for (int p = 0; p < 4; p++) bp[p] = pk2(bs[2 * p], bs[2 * p + 1]);
            #pragma unroll
            for (int i = 0; i < 8; i++)
                #pragma unroll
                for (int p = 0; p < 4; p++) fma2(acc[i][p], av[i], bp[p]);
        }
    }
    float s[8], q[8];
    #pragma unroll
    for (int j = 0; j < 8; j++) { s[j] = 0.f; q[j] = 0.f; }
    #pragma unroll
    for (int i = 0; i < 8; i++) {
        int nn = n0 + ty * 8 + i;
        if (nn >= n) continue;
        #pragma unroll
        for (int p = 0; p < 4; p++) {
            float2 f = upk2(acc[i][p]);
            int c0 = tx + 64 * p;
            float h0 = f.x + b2[c0];
            float h1v = f.y + b2[c0 + 32];
            g_h2pre[(size_t)nn * C2 + c0] = h0;
            g_h2pre[(size_t)nn * C2 + c0 + 32] = h1v;
            s[2 * p] += h0; q[2 * p] += h0 * h0;
            s[2 * p + 1] += h1v; q[2 * p + 1] += h1v * h1v;
        }
    }
    #pragma unroll
    for (int j = 0; j < 8; j++) {
        atomicAdd(&g_stats2[tx + 32 * j], s[j]);
        atomicAdd(&g_stats2[C2 + tx + 32 * j], q[j]);
    }
}

// ---------------- K6: BN + leaky relu -> h2 (into d_out) ----------------
__global__ void k_bn2(const float* __restrict__ gamma, const float* __restrict__ beta,
                      float* __restrict__ out, float nf, int n) {
    int i = blockIdx.x * blockDim.x + threadIdx.x;
    int tot = n * (C2 / 4);
    if (i >= tot) return;
    int cb = (i & (C2 / 4 - 1)) * 4;
    float4 h = ((const float4*)g_h2pre)[i];
    float hv[4] = {h.x, h.y, h.z, h.w};
    float o[4];
    #pragma unroll
    for (int c = 0; c < 4; c++) {
        float mu = g_stats2[cb + c] / nf;
        float var = g_stats2[C2 + cb + c] / nf - mu * mu;
        float sc = gamma[cb + c] * rsqrtf(var + EPSV);
        o[c] = lrelu(fmaf(sc, hv[c] - mu, beta[cb + c]));
    }
    ((float4*)out)[i] = make_float4(o[0], o[1], o[2], o[3]);
}

// ---------------- K7: u = h2 @ Wp1_top + bp1 ; v = h2 @ Wp1_bot ----------------
__global__ __launch_bounds__(256) void k_uv(const float* __restrict__ h2,
                                            const float* __restrict__ Wp1,
                                            const float* __restrict__ bp1, int n) {
    __shared__ float As[64 * 32];
    __shared__ float Bs[32 * 256];
    int t = threadIdx.x;
    int tx = t & 31, ty = t >> 5;
    int n0 = blockIdx.x * 64;
    unsigned long long acc[8][4];
    #pragma unroll
    for (int i = 0; i < 8; i++)
        #pragma unroll
        for (int p = 0; p < 4; p++) acc[i][p] = 0ull;
    for (int kk = 0; kk < C2; kk += 32) {
        __syncthreads();
        for (int i = t; i < 64 * 32; i += 256) {
            int nn = n0 + (i >> 5);
            As[i] = (nn < n) ? h2[(size_t)nn * C2 + kk + (i & 31)] : 0.f;
        }
        for (int i = t; i < 32 * 256; i += 256) {
            int k = i >> 8, c = i & 255;
            Bs[i] = (c < 128) ? Wp1[(size_t)(kk + k) * 128 + c]
                              : Wp1[(size_t)(256 + kk + k) * 128 + (c - 128)];
        }
        __syncthreads();
        #pragma unroll 8
        for (int k = 0; k < 32; k++) {
            unsigned long long av[8], bp[4];
            float bs[8];
            #pragma unroll
            for (int i = 0; i < 8; i++) { float a = As[(ty * 8 + i) * 32 + k]; av[i] = pk2(a, a); }
            #pragma unroll
            for (int j = 0; j < 8; j++) bs[j] = Bs[k * 256 + tx + 32 * j];
            #pragma unroll
            for (int p = 0; p < 4; p++) bp[p] = pk2(bs[2 * p], bs[2 * p + 1]);
            #pragma unroll
            for (int i = 0; i < 8; i++)
                #pragma unroll
                for (int p = 0; p < 4; p++) fma2(acc[i][p], av[i], bp[p]);
        }
    }
    #pragma unroll
    for (int i = 0; i < 8; i++) {
        int nn = n0 + ty * 8 + i;
        if (nn >= n) continue;
        #pragma unroll
        for (int p = 0; p < 4; p++) {
            float2 f = upk2(acc[i][p]);
            int c0 = tx + 64 * p;
            if (c0 < 128) {
                g_u[(size_t)nn * C1 + c0] = f.x + bp1[c0];
                g_u[(size_t)nn * C1 + c0 + 32] = f.y + bp1[c0 + 32];
            } else {
                g_v[(size_t)nn * C1 + c0 - 128] = f.x;
                g_v[(size_t)nn * C1 + c0 - 96] = f.y;
            }
        }
    }
}

// ---------------- K8: per-edge MLP: relu(u[s]+v[d]) @ Wp2 -> relu -> dot Wp3 -> sigmoid ----------------
__global__ __launch_bounds__(256) void k_edge(const int* __restrict__ src, const int* __restrict__ dst,
                                              const float* __restrict__ Wp2, const float* __restrict__ bp2,
                                              const float* __restrict__ Wp3, const float* __restrict__ bp3,
                                              float* __restrict__ pred, int E) {
    extern __shared__ float sm[];
    float* As = sm;                       // [k=128][e=128] -> 16384 floats
    float* Ws = sm + 16384;               // [k=128][c=64]  -> 8192 floats
    float* w3s = sm + 16384 + 8192;       // 64
    float* bp2s = w3s + 64;               // 64
    int t = threadIdx.x;
    int e0 = blockIdx.x * 128;
    if (t >= 128) {
        int tt = t - 128;
        for (int i = tt; i < 128 * 64; i += 128) Ws[i] = Wp2[i];
        if (tt < 64) { w3s[tt] = Wp3[tt]; bp2s[tt] = bp2[tt]; }
    } else {
        int e = e0 + t;
        if (e < E) {
            int s = src[e], d = dst[e];
            const float4* up = (const float4*)(g_u + (size_t)s * C1);
            const float4* vp = (const float4*)(g_v + (size_t)d * C1);
            #pragma unroll 8
            for (int i = 0; i < 32; i++) {
                float4 uu = up[i], vv = vp[i];
                int k = i * 4;
                float a0 = uu.x + vv.x, a1 = uu.y + vv.y, a2 = uu.z + vv.z, a3 = uu.w + vv.w;
                As[(k + 0) * 128 + t] = a0 > 0.f ? a0 : 0.f;
                As[(k + 1) * 128 + t] = a1 > 0.f ? a1 : 0.f;
                As[(k + 2) * 128 + t] = a2 > 0.f ? a2 : 0.f;
                As[(k + 3) * 128 + t] = a3 > 0.f ? a3 : 0.f;
            }
        } else {
            for (int k = 0; k < 128; k++) As[k * 128 + t] = 0.f;
        }
    }
    __syncthreads();
    int tx = t & 15, cg = t >> 4;
    const unsigned long long* Au = (const unsigned long long*)As;
    unsigned long long acc[4][4];
    #pragma unroll
    for (int p = 0; p < 4; p++)
        #pragma unroll
        for (int j = 0; j < 4; j++) acc[p][j] = 0ull;
    #pragma unroll 8
    for (int k = 0; k < 128; k++) {
        unsigned long long av[4];
        #pragma unroll
        for (int p = 0; p < 4; p++) av[p] = Au[k * 64 + tx + 16 * p];
        #pragma unroll
        for (int j = 0; j < 4; j++) {
            float w = Ws[k * 64 + cg + 16 * j];
            unsigned long long bw = pk2(w, w);
            #pragma unroll
            for (int p = 0; p < 4; p++) fma2(acc[p][j], av[p], bw);
        }
    }
    __syncthreads();  // done reading As; reuse as P
    float* P = sm;    // [e=128][c=64] stride 65
    #pragma unroll
    for (int p = 0; p < 4; p++) {
        int el = 2 * tx + 32 * p;
        #pragma unroll
        for (int j = 0; j < 4; j++) {
            int ch = cg + 16 * j;
            float2 f = upk2(acc[p][j]);
            float b = bp2s[ch];
            float y0 = f.x + b, y1 = f.y + b;
            P[el * 65 + ch] = y0 > 0.f ? y0 : 0.f;
            P[(el + 1) * 65 + ch] = y1 > 0.f ? y1 : 0.f;
        }
    }
    __syncthreads();
    if (t < 128) {
        int e = e0 + t;
        if (e < E) {
            float a3 = bp3[0];
            #pragma unroll
            for (int c = 0; c < 64; c++) a3 = fmaf(P[t * 65 + c], w3s[c], a3);
            pred[e] = 1.f / (1.f + expf(-a3));
        }
    }
}

// ---------------- launch ----------------
extern "C" void kernel_launch(void* const* d_in, const int* in_sizes, int n_in,
                              void* d_out, int out_size) {
    const float* x     = (const float*)d_in[0];
    const int*   ei    = (const int*)d_in[1];
    const float* W1    = (const float*)d_in[2];
    const float* b1    = (const float*)d_in[3];
    const float* ga1   = (const float*)d_in[4];
    const float* be1   = (const float*)d_in[5];
    const float* W2    = (const float*)d_in[6];
    const float* b2    = (const float*)d_in[7];
    const float* ga2   = (const float*)d_in[8];
    const float* be2   = (const float*)d_in[9];
    const float* Wp1   = (const float*)d_in[10];
    const float* bp1   = (const float*)d_in[11];
    const float* Wp2   = (const float*)d_in[12];
    const float* bp2   = (const float*)d_in[13];
    const float* Wp3   = (const float*)d_in[14];
    const float* bp3   = (const float*)d_in[15];

    int n = in_sizes[0] / NF;
    int E = in_sizes[1] / 2;
    const int* src = ei;
    const int* dst = ei + E;

    float* out  = (float*)d_out;
    float* h2   = out;
    float* pred = out + (size_t)n * C2;
    float nf = (float)n;

    k_init<<<(n * NF / 4 + 255) / 256, 256>>>(x, n);
    k_scatter_x<<<(E + 255) / 256, 256>>>(src, dst, x, E);
    k_rdeg<<<(n + 255) / 256, 256>>>(n);
    k_gcn1<<<(n + 63) / 64, 128>>>(W1, b1, n);
    k_bn1<<<(n * (C1 / 4) + 255) / 256, 256>>>(ga1, be1, nf, n);
    k_scatter_h<<<(E * 8 + 255) / 256, 256>>>(src, dst, E);
    k_gcn2<<<(n + 63) / 64, 256>>>(W2, b2, n);
    k_bn2<<<(n * (C2 / 4) + 255) / 256, 256>>>(ga2, be2, h2, nf, n);
    k_uv<<<(n + 63) / 64, 256>>>(h2, Wp1, bp1, n);

    static int smem_set = 0;
    if (!smem_set) {
        cudaFuncSetAttribute(k_edge, cudaFuncAttributeMaxDynamicSharedMemorySize, 100 * 1024);
        smem_set = 1;
    }
    k_edge<<<(E + 127) / 128, 256, (16384 + 8192 + 128 + 16) * 4>>>(src, dst, Wp2, bp2, Wp3, bp3, pred, E);
}

// round 2
// speedup vs baseline: 1.1142x; 1.1142x over previous
#include <cuda_runtime.h>
#include <math.h>

#define NN 100000
#define NF 16
#define C1 128
#define C2 256
#define EPSV 1e-5f

// ---------------- scratch ----------------
__device__ float g_aggx[NN * NF];
__device__ float g_deg[NN];
__device__ float g_rdeg[NN];
__device__ float g_h1[NN * C1];
__device__ float g_agg1[NN * C1];
__device__ float g_h2pre[NN * C2];
__device__ float g_u[NN * C1];
__device__ float g_v[NN * C1];
__device__ float g_stats1[2 * C1];
__device__ float g_stats2[2 * C2];

// ---------------- helpers ----------------
__device__ __forceinline__ void red_add_v4(float* p, float4 v) {
    asm volatile("red.global.add.v4.f32 [%0], {%1, %2, %3, %4};"
                 :: "l"(p), "f"(v.x), "f"(v.y), "f"(v.z), "f"(v.w) : "memory");
}
__device__ __forceinline__ float lrelu(float y) { return y > 0.f ? y : 0.01f * y; }
__device__ __forceinline__ unsigned tf32r(float x) {
    unsigned r; asm("cvt.rna.tf32.f32 %0, %1;" : "=r"(r) : "f"(x)); return r;
}
__device__ __forceinline__ void mma8(float4& d, const unsigned a[4], unsigned b0, unsigned b1) {
    asm volatile("mma.sync.aligned.m16n8k8.row.col.f32.tf32.tf32.f32 "
                 "{%0,%1,%2,%3},{%4,%5,%6,%7},{%8,%9},{%0,%1,%2,%3};"
                 : "+f"(d.x), "+f"(d.y), "+f"(d.z), "+f"(d.w)
                 : "r"(a[0]), "r"(a[1]), "r"(a[2]), "r"(a[3]), "r"(b0), "r"(b1));
}

// ---------------- K0: init ----------------
__global__ void k_init(const float* __restrict__ x, int n) {
    int i = blockIdx.x * blockDim.x + threadIdx.x;
    int tot = n * NF / 4;
    if (i < tot) ((float4*)g_aggx)[i] = ((const float4*)x)[i];
    if (i < n) g_deg[i] = 1.f;
    if (i < 2 * C1) g_stats1[i] = 0.f;
    if (i < 2 * C2) g_stats2[i] = 0.f;
}

// ---------------- K1: scatter x, deg ----------------
__global__ void k_scatter_x(const int* __restrict__ src, const int* __restrict__ dst,
                            const float* __restrict__ x, int E) {
    int e = blockIdx.x * blockDim.x + threadIdx.x;
    if (e >= E) return;
    int s = src[e], d = dst[e];
    const float4* xs = (const float4*)(x + (size_t)s * NF);
    float* ad = g_aggx + (size_t)d * NF;
    red_add_v4(ad + 0, xs[0]);
    red_add_v4(ad + 4, xs[1]);
    red_add_v4(ad + 8, xs[2]);
    red_add_v4(ad + 12, xs[3]);
    atomicAdd(&g_deg[d], 1.f);
}

__global__ void k_rdeg(int n) {
    int i = blockIdx.x * blockDim.x + threadIdx.x;
    if (i < n) g_rdeg[i] = 1.f / g_deg[i];
}

// ---------------- K2: h1pre = (aggx/deg) @ W1 + b1, BN1 stats ----------------
__global__ __launch_bounds__(256) void k_gcn1(const float* __restrict__ W1,
                                              const float* __restrict__ b1, int n) {
    __shared__ float W1s[NF * C1];
    __shared__ float xs[64 * NF];
    __shared__ float rds[64];
    int t = threadIdx.x;
    for (int i = t; i < NF * C1; i += 256) W1s[i] = W1[i];
    int n0 = blockIdx.x * 64;
    for (int i = t; i < 64 * NF; i += 256) {
        int nn = n0 + (i >> 4);
        xs[i] = (nn < n) ? g_aggx[(size_t)nn * NF + (i & 15)] : 0.f;
    }
    if (t < 64) rds[t] = (n0 + t < n) ? g_rdeg[n0 + t] : 0.f;
    __syncthreads();
    int c = t & 127, half = t >> 7;
    float bc = b1[c];
    float s = 0.f, q = 0.f;
    for (int j = half * 32; j < half * 32 + 32; j++) {
        int nn = n0 + j;
        if (nn >= n) break;
        float acc = 0.f;
        #pragma unroll
        for (int k = 0; k < NF; k++) acc = fmaf(xs[j * NF + k], W1s[k * C1 + c], acc);
        float h = fmaf(acc, rds[j], bc);
        g_h1[(size_t)nn * C1 + c] = h;
        s += h; q += h * h;
    }
    atomicAdd(&g_stats1[c], s);
    atomicAdd(&g_stats1[C1 + c], q);
}

// ---------------- K3: BN1 + leaky relu; init agg1 ----------------
__global__ void k_bn1(const float* __restrict__ gamma, const float* __restrict__ beta,
                      float nf, int n) {
    int i = blockIdx.x * blockDim.x + threadIdx.x;
    int tot = n * (C1 / 4);
    if (i >= tot) return;
    int cb = (i & (C1 / 4 - 1)) * 4;
    float4 h = ((const float4*)g_h1)[i];
    float hv[4] = {h.x, h.y, h.z, h.w};
    float o[4];
    #pragma unroll
    for (int c = 0; c < 4; c++) {
        float mu = g_stats1[cb + c] / nf;
        float var = g_stats1[C1 + cb + c] / nf - mu * mu;
        float sc = gamma[cb + c] * rsqrtf(var + EPSV);
        o[c] = lrelu(fmaf(sc, hv[c] - mu, beta[cb + c]));
    }
    float4 r = make_float4(o[0], o[1], o[2], o[3]);
    ((float4*)g_h1)[i] = r;
    ((float4*)g_agg1)[i] = r;
}

// ---------------- K4: scatter h1 ----------------
__global__ void k_scatter_h(const int* __restrict__ src, const int* __restrict__ dst, int E) {
    int t = blockIdx.x * blockDim.x + threadIdx.x;
    if (t >= E * 8) return;
    int e = t >> 3;
    int ch = (t & 7) * 16;
    int s = src[e], d = dst[e];
    const float4* hs = (const float4*)(g_h1 + (size_t)s * C1 + ch);
    float* ad = g_agg1 + (size_t)d * C1 + ch;
    red_add_v4(ad + 0, hs[0]);
    red_add_v4(ad + 4, hs[1]);
    red_add_v4(ad + 8, hs[2]);
    red_add_v4(ad + 12, hs[3]);
}

// ---------------- K5: h2pre = (agg1/deg) @ W2 + b2  (tf32 tensor cores) ----------------
// block: 64 rows x 256 cols, 8 warps (4 row-groups x 2 col-groups), warp = 16x128
#define AST 36
#define BST 264
__global__ __launch_bounds__(256) void k_gcn2(const float* __restrict__ W2,
                                              const float* __restrict__ b2, int n) {
    __shared__ unsigned As[64 * AST];
    __shared__ unsigned Bs[32 * BST];
    __shared__ float rds[64];
    int t = threadIdx.x;
    int lane = t & 31, warp = t >> 5;
    int wr = warp >> 1, wc = warp & 1;
    int n0 = blockIdx.x * 64;
    if (t < 64) rds[t] = (n0 + t < n) ? g_rdeg[n0 + t] : 0.f;
    float4 acc[16];
    #pragma unroll
    for (int j = 0; j < 16; j++) acc[j] = make_float4(0.f, 0.f, 0.f, 0.f);
    for (int kk = 0; kk < C1; kk += 32) {
        __syncthreads();
        for (int i = t; i < 64 * 32; i += 256) {
            int r = i >> 5, k = i & 31;
            int nn = n0 + r;
            float vv = (nn < n) ? g_agg1[(size_t)nn * C1 + kk + k] * rds[r] : 0.f;
            As[r * AST + k] = tf32r(vv);
        }
        for (int i = t; i < 32 * 256; i += 256) {
            int k = i >> 8, c = i & 255;
            Bs[k * BST + c] = tf32r(W2[(size_t)(kk + k) * C2 + c]);
        }
        __syncthreads();
        #pragma unroll
        for (int ks = 0; ks < 4; ks++) {
            int k0 = ks * 8;
            unsigned a[4];
            int r0 = wr * 16 + (lane >> 2);
            a[0] = As[r0 * AST + k0 + (lane & 3)];
            a[1] = As[(r0 + 8) * AST + k0 + (lane & 3)];
            a[2] = As[r0 * AST + k0 + 4 + (lane & 3)];
            a[3] = As[(r0 + 8) * AST + k0 + 4 + (lane & 3)];
            #pragma unroll
            for (int j = 0; j < 16; j++) {
                int nn0 = wc * 128 + 8 * j;
                unsigned b0 = Bs[(k0 + (lane & 3)) * BST + nn0 + (lane >> 2)];
                unsigned b1 = Bs[(k0 + 4 + (lane & 3)) * BST + nn0 + (lane >> 2)];
                mma8(acc[j], a, b0, b1);
            }
        }
    }
    int r0 = n0 + wr * 16 + (lane >> 2);
    #pragma unroll
    for (int j = 0; j < 16; j++) {
        int c0 = wc * 128 + 8 * j + 2 * (lane & 3);
        float2 bb = make_float2(b2[c0], b2[c0 + 1]);
        if (r0 < n) {
            float2 s0 = make_float2(acc[j].x + bb.x, acc[j].y + bb.y);
            *(float2*)&g_h2pre[(size_t)r0 * C2 + c0] = s0;
        }
        if (r0 + 8 < n) {
            float2 s1 = make_float2(acc[j].z + bb.x, acc[j].w + bb.y);
            *(float2*)&g_h2pre[(size_t)(r0 + 8) * C2 + c0] = s1;
        }
    }
}

// ---------------- K5b: BN2 stats from h2pre ----------------
__global__ __launch_bounds__(256) void k_stats2(int n) {
    int col = threadIdx.x;
    int r0 = blockIdx.x * 256;
    int r1 = min(r0 + 256, n);
    float s = 0.f, q = 0.f;
    for (int r = r0; r < r1; r++) {
        float h = g_h2pre[(size_t)r * C2 + col];
        s += h; q += h * h;
    }
    atomicAdd(&g_stats2[col], s);
    atomicAdd(&g_stats2[C2 + col], q);
}

// ---------------- K6: BN2 + leaky relu -> h2 (d_out) ----------------
__global__ void k_bn2(const float* __restrict__ gamma, const float* __restrict__ beta,
                      float* __restrict__ out, float nf, int n) {
    int i = blockIdx.x * blockDim.x + threadIdx.x;
    int tot = n * (C2 / 4);
    if (i >= tot) return;
    int cb = (i & (C2 / 4 - 1)) * 4;
    float4 h = ((const float4*)g_h2pre)[i];
    float hv[4] = {h.x, h.y, h.z, h.w};
    float o[4];
    #pragma unroll
    for (int c = 0; c < 4; c++) {
        float mu = g_stats2[cb + c] / nf;
        float var = g_stats2[C2 + cb + c] / nf - mu * mu;
        float sc = gamma[cb + c] * rsqrtf(var + EPSV);
        o[c] = lrelu(fmaf(sc, hv[c] - mu, beta[cb + c]));
    }
    ((float4*)out)[i] = make_float4(o[0], o[1], o[2], o[3]);
}

// ---------------- K7: u = h2 @ Wp1_top + bp1 ; v = h2 @ Wp1_bot  (tf32) ----------------
__global__ __launch_bounds__(256) void k_uv(const float* __restrict__ h2,
                                            const float* __restrict__ Wp1,
                                            const float* __restrict__ bp1, int n) {
    __shared__ unsigned As[64 * AST];
    __shared__ unsigned Bs[32 * BST];
    int t = threadIdx.x;
    int lane = t & 31, warp = t >> 5;
    int wr = warp >> 1, wc = warp & 1;
    int n0 = blockIdx.x * 64;
    float4 acc[16];
    #pragma unroll
    for (int j = 0; j < 16; j++) acc[j] = make_float4(0.f, 0.f, 0.f, 0.f);
    for (int kk = 0; kk < C2; kk += 32) {
        __syncthreads();
        for (int i = t; i < 64 * 32; i += 256) {
            int r = i >> 5, k = i & 31;
            int nn = n0 + r;
            float vv = (nn < n) ? h2[(size_t)nn * C2 + kk + k] : 0.f;
            As[r * AST + k] = tf32r(vv);
        }
        for (int i = t; i < 32 * 256; i += 256) {
            int k = i >> 8, c = i & 255;
            float vv = (c < 128) ? Wp1[(size_t)(kk + k) * 128 + c]
                                 : Wp1[(size_t)(256 + kk + k) * 128 + (c - 128)];
            Bs[k * BST + c] = tf32r(vv);
        }
        __syncthreads();
        #pragma unroll
        for (int ks = 0; ks < 4; ks++) {
            int k0 = ks * 8;
            unsigned a[4];
            int r0 = wr * 16 + (lane >> 2);
            a[0] = As[r0 * AST + k0 + (lane & 3)];
            a[1] = As[(r0 + 8) * AST + k0 + (lane & 3)];
            a[2] = As[r0 * AST + k0 + 4 + (lane & 3)];
            a[3] = As[(r0 + 8) * AST + k0 + 4 + (lane & 3)];
            #pragma unroll
            for (int j = 0; j < 16; j++) {
                int nn0 = wc * 128 + 8 * j;
                unsigned b0 = Bs[(k0 + (lane & 3)) * BST + nn0 + (lane >> 2)];
                unsigned b1 = Bs[(k0 + 4 + (lane & 3)) * BST + nn0 + (lane >> 2)];
                mma8(acc[j], a, b0, b1);
            }
        }
    }
    int r0 = n0 + wr * 16 + (lane >> 2);
    #pragma unroll
    for (int j = 0; j < 16; j++) {
        int c0 = wc * 128 + 8 * j + 2 * (lane & 3);
        if (wc == 0) {
            float2 bb = make_float2(bp1[c0], bp1[c0 + 1]);
            if (r0 < n)
                *(float2*)&g_u[(size_t)r0 * C1 + c0] =
                    make_float2(acc[j].x + bb.x, acc[j].y + bb.y);
            if (r0 + 8 < n)
                *(float2*)&g_u[(size_t)(r0 + 8) * C1 + c0] =
                    make_float2(acc[j].z + bb.x, acc[j].w + bb.y);
        } else {
            int cv = c0 - 128;
            if (r0 < n)
                *(float2*)&g_v[(size_t)r0 * C1 + cv] = make_float2(acc[j].x, acc[j].y);
            if (r0 + 8 < n)
                *(float2*)&g_v[(size_t)(r0 + 8) * C1 + cv] = make_float2(acc[j].z, acc[j].w);
        }
    }
}

// ---------------- K8: per-edge MLP (tf32 tensor cores) ----------------
// tile = 128 edges; smem: As[128][132] tf32, Ws[128][72] tf32, w3s/bp2s
#define EAST 132
#define EWST 72
#define EPST 66
__global__ __launch_bounds__(256) void k_edge(const int* __restrict__ src, const int* __restrict__ dst,
                                              const float* __restrict__ Wp2, const float* __restrict__ bp2,
                                              const float* __restrict__ Wp3, const float* __restrict__ bp3,
                                              float* __restrict__ pred, int E) {
    extern __shared__ unsigned smx[];
    unsigned* As = smx;                            // 128*132
    unsigned* Ws = smx + 128 * EAST;               // 128*72
    float* w3s = (float*)(Ws + 128 * EWST);        // 64
    float* bp2s = w3s + 64;                        // 64
    int t = threadIdx.x;
    int lane = t & 31, warp = t >> 5;
    int e0 = blockIdx.x * 128;

    // gather phase: 2 threads per edge, 64 k each
    {
        int el = t >> 1, half = t & 1;
        int e = e0 + el;
        unsigned* row = As + el * EAST + 64 * half;
        if (e < E) {
            int s = src[e], d = dst[e];
            const float4* up = (const float4*)(g_u + (size_t)s * C1 + 64 * half);
            const float4* vp = (const float4*)(g_v + (size_t)d * C1 + 64 * half);
            #pragma unroll
            for (int i = 0; i < 16; i++) {
                float4 uu = up[i], vv = vp[i];
                float a0 = uu.x + vv.x, a1 = uu.y + vv.y;
                float a2 = uu.z + vv.z, a3 = uu.w + vv.w;
                row[4 * i + 0] = tf32r(a0 > 0.f ? a0 : 0.f);
                row[4 * i + 1] = tf32r(a1 > 0.f ? a1 : 0.f);
                row[4 * i + 2] = tf32r(a2 > 0.f ? a2 : 0.f);
                row[4 * i + 3] = tf32r(a3 > 0.f ? a3 : 0.f);
            }
        } else {
            #pragma unroll
            for (int i = 0; i < 64; i++) row[i] = 0u;
        }
    }
    // weights
    for (int i = t; i < 128 * 64; i += 256) {
        int k = i >> 6, c = i & 63;
        Ws[k * EWST + c] = tf32r(Wp2[i]);
    }
    if (t < 64) { w3s[t] = Wp3[t]; bp2s[t] = bp2[t]; }
    __syncthreads();

    // mma: warp handles 16 edges x 64 cols
    float4 acc[8];
    #pragma unroll
    for (int j = 0; j < 8; j++) acc[j] = make_float4(0.f, 0.f, 0.f, 0.f);
    int r0 = warp * 16 + (lane >> 2);
    #pragma unroll
    for (int ks = 0; ks < 16; ks++) {
        int k0 = ks * 8;
        unsigned a[4];
        a[0] = As[r0 * EAST + k0 + (lane & 3)];
        a[1] = As[(r0 + 8) * EAST + k0 + (lane & 3)];
        a[2] = As[r0 * EAST + k0 + 4 + (lane & 3)];
        a[3] = As[(r0 + 8) * EAST + k0 + 4 + (lane & 3)];
        #pragma unroll
        for (int j = 0; j < 8; j++) {
            unsigned b0 = Ws[(k0 + (lane & 3)) * EWST + 8 * j + (lane >> 2)];
            unsigned b1 = Ws[(k0 + 4 + (lane & 3)) * EWST + 8 * j + (lane >> 2)];
            mma8(acc[j], a, b0, b1);
        }
    }
    __syncthreads();  // As reads done; reuse as P
    float* P = (float*)As;  // [128 edges][stride 66]
    #pragma unroll
    for (int j = 0; j < 8; j++) {
        int c0 = 8 * j + 2 * (lane & 3);
        float b0v = bp2s[c0], b1v = bp2s[c0 + 1];
        float y;
        y = acc[j].x + b0v; P[r0 * EPST + c0] = y > 0.f ? y : 0.f;
        y = acc[j].y + b1v; P[r0 * EPST + c0 + 1] = y > 0.f ? y : 0.f;
        y = acc[j].z + b0v; P[(r0 + 8) * EPST + c0] = y > 0.f ? y : 0.f;
        y = acc[j].w + b1v; P[(r0 + 8) * EPST + c0 + 1] = y > 0.f ? y : 0.f;
    }
    __syncthreads();
    if (t < 128) {
        int e = e0 + t;
        if (e < E) {
            float a3 = bp3[0];
            #pragma unroll
            for (int c = 0; c < 64; c++) a3 = fmaf(P[t * EPST + c], w3s[c], a3);
            pred[e] = 1.f / (1.f + expf(-a3));
        }
    }
}

// ---------------- launch ----------------
extern "C" void kernel_launch(void* const* d_in, const int* in_sizes, int n_in,
                              void* d_out, int out_size) {
    const float* x   = (const float*)d_in[0];
    const int*   ei  = (const int*)d_in[1];
    const float* W1  = (const float*)d_in[2];
    const float* b1  = (const float*)d_in[3];
    const float* ga1 = (const float*)d_in[4];
    const float* be1 = (const float*)d_in[5];
    const float* W2  = (const float*)d_in[6];
    const float* b2  = (const float*)d_in[7];
    const float* ga2 = (const float*)d_in[8];
    const float* be2 = (const float*)d_in[9];
    const float* Wp1 = (const float*)d_in[10];
    const float* bp1 = (const float*)d_in[11];
    const float* Wp2 = (const float*)d_in[12];
    const float* bp2 = (const float*)d_in[13];
    const float* Wp3 = (const float*)d_in[14];
    const float* bp3 = (const float*)d_in[15];

    int n = in_sizes[0] / NF;
    int E = in_sizes[1] / 2;
    const int* src = ei;
    const int* dst = ei + E;

    float* out  = (float*)d_out;
    float* h2   = out;
    float* pred = out + (size_t)n * C2;
    float nf = (float)n;

    k_init<<<(n * NF / 4 + 255) / 256, 256>>>(x, n);
    k_scatter_x<<<(E + 255) / 256, 256>>>(src, dst, x, E);
    k_rdeg<<<(n + 255) / 256, 256>>>(n);
    k_gcn1<<<(n + 63) / 64, 256>>>(W1, b1, n);
    k_bn1<<<(n * (C1 / 4) + 255) / 256, 256>>>(ga1, be1, nf, n);
    k_scatter_h<<<(E * 8 + 255) / 256, 256>>>(src, dst, E);
    k_gcn2<<<(n + 63) / 64, 256>>>(W2, b2, n);
    k_stats2<<<(n + 255) / 256, 256>>>(n);
    k_bn2<<<(n * (C2 / 4) + 255) / 256, 256>>>(ga2, be2, h2, nf, n);
    k_uv<<<(n + 63) / 64, 256>>>(h2, Wp1, bp1, n);

    static int smem_set = 0;
    if (!smem_set) {
        cudaFuncSetAttribute(k_edge, cudaFuncAttributeMaxDynamicSharedMemorySize, 112 * 1024);
        smem_set = 1;
    }
    size_t esm = (size_t)(128 * EAST + 128 * EWST + 128) * 4;
    k_edge<<<(E + 127) / 128, 256, esm>>>(src, dst, Wp2, bp2, Wp3, bp3, pred, E);
}